// round 5
// baseline (speedup 1.0000x reference)
#include <cuda_runtime.h>

// Problem constants
#define BATCH  256
#define DI     5120
#define RNK    160
#define NS     16
#define NC     192          // 160 (W_delta) + 16 (W_B) + 16 (W_C) concatenated
#define KSPLIT 32
#define KCHUNK 160          // 5120 / 32

// Scratch (device globals: no allocations allowed)
__device__ float g_Ppart[KSPLIT * BATCH * NC];   // split-K partials for GEMM1
__device__ float g_P[BATCH * NC];                // reduced: [xd | Bp | C] per batch row
__device__ float g_negA[DI * NS];                // -exp(A_log)
__device__ float g_dt[BATCH * DI];               // softplus(xd @ W_dt + b_dt)

// ---------------------------------------------------------------------------
// K1: GEMM1  P_part = X(256x5120) @ [W_delta | W_B | W_C] (5120x192), split-K.
// grid = (3 n-tiles, 4 m-tiles, 32 k-splits), block = 256 threads,
// tile 64x64, TK=32, per-thread 4x4 register tile.
// ---------------------------------------------------------------------------
__global__ __launch_bounds__(256)
void k1_gemm1(const float* __restrict__ X,
              const float* __restrict__ Wd,
              const float* __restrict__ WB,
              const float* __restrict__ WC)
{
    __shared__ float Xs[64][32];   // [m][k] — conflict-free writes, broadcast reads
    __shared__ float Ws[32][64];   // [k][n] — float4 reads along n

    const int n0 = blockIdx.x * 64;
    const int m0 = blockIdx.y * 64;
    const int k0 = blockIdx.z * KCHUNK;
    const int tid = threadIdx.x;
    const int tx = tid & 15;       // n / 4
    const int ty = tid >> 4;       // m / 4

    float acc[4][4] = {};

    const int lk  = tid & 31;      // X load: k within tile
    const int lm  = tid >> 5;      // X load: m base (0..7)
    const int lj  = tid & 63;      // W load: n within tile
    const int lk4 = tid >> 6;      // W load: k base (0..3)
    const int jg  = n0 + lj;       // global concat-column

    for (int kt = 0; kt < KCHUNK; kt += 32) {
        // Load X tile 64x32 (coalesced along k)
        #pragma unroll
        for (int i = 0; i < 8; i++) {
            int m = i * 8 + lm;
            Xs[m][lk] = X[(size_t)(m0 + m) * DI + (k0 + kt + lk)];
        }
        // Load W tile 32x64 from the concatenated [W_delta | W_B | W_C]
        #pragma unroll
        for (int i = 0; i < 8; i++) {
            int k  = i * 4 + lk4;
            int kg = k0 + kt + k;
            float w;
            if (jg < 160)       w = Wd[(size_t)kg * 160 + jg];
            else if (jg < 176)  w = WB[(size_t)kg * 16 + (jg - 160)];
            else                w = WC[(size_t)kg * 16 + (jg - 176)];
            Ws[k][lj] = w;
        }
        __syncthreads();

        #pragma unroll
        for (int kk = 0; kk < 32; kk++) {
            float4 wv = *(const float4*)&Ws[kk][tx * 4];
            float a0 = Xs[ty * 4 + 0][kk];
            float a1 = Xs[ty * 4 + 1][kk];
            float a2 = Xs[ty * 4 + 2][kk];
            float a3 = Xs[ty * 4 + 3][kk];
            acc[0][0] = fmaf(a0, wv.x, acc[0][0]); acc[0][1] = fmaf(a0, wv.y, acc[0][1]);
            acc[0][2] = fmaf(a0, wv.z, acc[0][2]); acc[0][3] = fmaf(a0, wv.w, acc[0][3]);
            acc[1][0] = fmaf(a1, wv.x, acc[1][0]); acc[1][1] = fmaf(a1, wv.y, acc[1][1]);
            acc[1][2] = fmaf(a1, wv.z, acc[1][2]); acc[1][3] = fmaf(a1, wv.w, acc[1][3]);
            acc[2][0] = fmaf(a2, wv.x, acc[2][0]); acc[2][1] = fmaf(a2, wv.y, acc[2][1]);
            acc[2][2] = fmaf(a2, wv.z, acc[2][2]); acc[2][3] = fmaf(a2, wv.w, acc[2][3]);
            acc[3][0] = fmaf(a3, wv.x, acc[3][0]); acc[3][1] = fmaf(a3, wv.y, acc[3][1]);
            acc[3][2] = fmaf(a3, wv.z, acc[3][2]); acc[3][3] = fmaf(a3, wv.w, acc[3][3]);
        }
        __syncthreads();
    }

    float* out = g_Ppart + (size_t)blockIdx.z * (BATCH * NC);
    #pragma unroll
    for (int i = 0; i < 4; i++)
        #pragma unroll
        for (int j = 0; j < 4; j++)
            out[(size_t)(m0 + ty * 4 + i) * NC + (n0 + tx * 4 + j)] = acc[i][j];
}

// ---------------------------------------------------------------------------
// K1b: reduce split-K partials -> g_P, and precompute g_negA = -exp(A_log).
// ---------------------------------------------------------------------------
__global__ __launch_bounds__(256)
void k1b_reduce(const float* __restrict__ A_log)
{
    int i = blockIdx.x * 256 + threadIdx.x;
    if (i < BATCH * NC) {
        float s = 0.f;
        #pragma unroll
        for (int p = 0; p < KSPLIT; p++)
            s += g_Ppart[(size_t)p * (BATCH * NC) + i];
        g_P[i] = s;
    }
    if (i < DI * NS)
        g_negA[i] = -__expf(A_log[i]);
}

// ---------------------------------------------------------------------------
// K2: GEMM2  dt = softplus(xd(256x160) @ W_dt(160x5120) + b_dt).
// grid = (80 n-tiles, 8 m-tiles), block = 256, tile 32x64, TK=32,
// per-thread 2x4 register tile. 640 blocks -> good wave balance.
// ---------------------------------------------------------------------------
__global__ __launch_bounds__(256)
void k2_gemm2(const float* __restrict__ Wdt,
              const float* __restrict__ bdt)
{
    __shared__ float Xs[32][32];   // [m(b)][k(r)]
    __shared__ float Ws[32][64];   // [k(r)][n(d)]

    const int n0 = blockIdx.x * 64;
    const int m0 = blockIdx.y * 32;
    const int tid = threadIdx.x;
    const int tx = tid & 15;       // n / 4
    const int ty = tid >> 4;       // m / 2 (0..15)

    float acc[2][4] = {};

    const int lk  = tid & 31;
    const int lm  = tid >> 5;      // 0..7
    const int lj  = tid & 63;
    const int lk4 = tid >> 6;      // 0..3

    for (int kt = 0; kt < RNK; kt += 32) {
        // X tile 32x32 from g_P (xd = first 160 columns, row stride NC)
        #pragma unroll
        for (int i = 0; i < 4; i++) {
            int m = i * 8 + lm;
            Xs[m][lk] = g_P[(size_t)(m0 + m) * NC + (kt + lk)];
        }
        // W tile 32x64 from W_dt (row-major 160 x 5120)
        #pragma unroll
        for (int i = 0; i < 8; i++) {
            int k = i * 4 + lk4;
            Ws[k][lj] = Wdt[(size_t)(kt + k) * DI + (n0 + lj)];
        }
        __syncthreads();

        #pragma unroll
        for (int kk = 0; kk < 32; kk++) {
            float4 wv = *(const float4*)&Ws[kk][tx * 4];
            float a0 = Xs[ty * 2 + 0][kk];
            float a1 = Xs[ty * 2 + 1][kk];
            acc[0][0] = fmaf(a0, wv.x, acc[0][0]); acc[0][1] = fmaf(a0, wv.y, acc[0][1]);
            acc[0][2] = fmaf(a0, wv.z, acc[0][2]); acc[0][3] = fmaf(a0, wv.w, acc[0][3]);
            acc[1][0] = fmaf(a1, wv.x, acc[1][0]); acc[1][1] = fmaf(a1, wv.y, acc[1][1]);
            acc[1][2] = fmaf(a1, wv.z, acc[1][2]); acc[1][3] = fmaf(a1, wv.w, acc[1][3]);
        }
        __syncthreads();
    }

    #pragma unroll
    for (int i = 0; i < 2; i++) {
        #pragma unroll
        for (int j = 0; j < 4; j++) {
            int dg = n0 + tx * 4 + j;
            float z = acc[i][j] + bdt[dg];
            // softplus with threshold 20 (matches reference)
            float sp = (z > 20.f) ? z : log1pf(__expf(z));
            g_dt[(size_t)(m0 + ty * 2 + i) * DI + dg] = sp;
        }
    }
}

// ---------------------------------------------------------------------------
// K3: fused elementwise + state readout (memory bound, h never written back).
// y[b,d] = sum_n exp(dt*negA[d,n])*h[b,d,n]*C[b,n] + dt*x*(Bp.C) + x*D[d]
// One thread per (b,d); h/negA read as 4x float4.
// ---------------------------------------------------------------------------
__global__ __launch_bounds__(256)
void k3_main(const float* __restrict__ x,
             const float* __restrict__ h,
             const float* __restrict__ Dv,
             float* __restrict__ y)
{
    int idx = blockIdx.x * 256 + threadIdx.x;   // < BATCH*DI
    int b = idx / DI;
    int d = idx - b * DI;

    float dt = g_dt[idx];
    float xv = x[idx];

    const float4* hp = (const float4*)(h + (size_t)idx * NS);
    const float4* ap = (const float4*)(g_negA + (size_t)d * NS);
    const float*  Pb = g_P + (size_t)b * NC;

    float acc = 0.f;
    float bc  = 0.f;
    #pragma unroll
    for (int q = 0; q < 4; q++) {
        float4 hv = hp[q];
        float4 av = ap[q];
        float4 cv = *(const float4*)&Pb[176 + q * 4];   // C[b, 4q..4q+3]
        float4 bv = *(const float4*)&Pb[160 + q * 4];   // Bp[b, 4q..4q+3]
        acc = fmaf(__expf(dt * av.x) * hv.x, cv.x, acc);
        acc = fmaf(__expf(dt * av.y) * hv.y, cv.y, acc);
        acc = fmaf(__expf(dt * av.z) * hv.z, cv.z, acc);
        acc = fmaf(__expf(dt * av.w) * hv.w, cv.w, acc);
        bc  = fmaf(bv.x, cv.x, bc);
        bc  = fmaf(bv.y, cv.y, bc);
        bc  = fmaf(bv.z, cv.z, bc);
        bc  = fmaf(bv.w, cv.w, bc);
    }
    y[idx] = acc + dt * xv * bc + xv * Dv[d];
}

// ---------------------------------------------------------------------------
// Launch: 4 kernels, stream-ordered dependencies, graph-capturable,
// no allocations, no atomics (bitwise deterministic).
// Input order (metadata): x, h, W_delta, W_dt, b_dt, A_log, W_B, W_C, D
// ---------------------------------------------------------------------------
extern "C" void kernel_launch(void* const* d_in, const int* in_sizes, int n_in,
                              void* d_out, int out_size)
{
    const float* x      = (const float*)d_in[0];
    const float* h      = (const float*)d_in[1];
    const float* Wdelta = (const float*)d_in[2];
    const float* Wdt    = (const float*)d_in[3];
    const float* bdt    = (const float*)d_in[4];
    const float* Alog   = (const float*)d_in[5];
    const float* WB     = (const float*)d_in[6];
    const float* WC     = (const float*)d_in[7];
    const float* Dv     = (const float*)d_in[8];
    float* y = (float*)d_out;

    dim3 g1(NC / 64, BATCH / 64, KSPLIT);            // 3 x 4 x 32 = 384 blocks
    k1_gemm1<<<g1, 256>>>(x, Wdelta, WB, WC);

    k1b_reduce<<<(DI * NS + 255) / 256, 256>>>(Alog); // 320 blocks

    dim3 g2(DI / 64, BATCH / 32);                    // 80 x 8 = 640 blocks
    k2_gemm2<<<g2, 256>>>(Wdt, bdt);

    k3_main<<<(BATCH * DI) / 256, 256>>>(x, h, Dv, y); // 5120 blocks
}